// round 8
// baseline (speedup 1.0000x reference)
#include <cuda_runtime.h>
#include <cuda_bf16.h>
#include <cstdint>

// ---------------- problem constants ----------------
#define NC     81
#define NROWS  1200          // B*Q
#define HOUT   160
#define POUT   25600         // 160*160
#define MT     400           // num targets
#define HIN    256

// ---------------- GEMM constants -------------------
#define GM 2432              // 2*1200 padded to 19*128
#define GN 512               // 400 padded to 2*256
#define GK 25600
#define BM 128
#define BN 256
#define BK 32
#define MTILES 19
#define NTILES 2
#define MAXSPLIT 4
#define NCHUNKS 800          // GK/BK
#define STAGES 4
#define LDKROW 40            // padded smem row: 40 bf16 = 80B

#define SM_A_BYTES (BM * LDKROW * 2)              // 10240
#define SM_B_BYTES (BN * LDKROW * 2)              // 20480
#define SM_STAGE   (SM_A_BYTES + SM_B_BYTES)      // 30720
#define GEMM_SMEM  (STAGES * SM_STAGE)            // 122880

#define RESIZE_LD   257
#define RESIZE_SMEM (HOUT * RESIZE_LD * 4)        // 164480

// ---------------- scratch (device globals; zero-initialized) ----------------
__device__ __align__(16) __nv_bfloat16 g_A[(size_t)GM * GK];  // [X; sigmoid(X)], pad rows 0
__device__ __align__(16) __nv_bfloat16 g_T[(size_t)GN * GK];  // resized targets, pad rows 0
__device__ float g_Sp[(size_t)MAXSPLIT * GM * GN];            // K-split partials (unwritten stay 0)
__device__ float g_L[NROWS];                                  // rowsum log_sigmoid(-x)
__device__ float g_P[NROWS];                                  // rowsum sigmoid(x)
__device__ float g_TS[MT];                                    // target mask sums
__device__ float g_prob[NROWS * NC];                          // softmax probs

// ---------------- helpers ----------------
__device__ __forceinline__ float2 blockReduceSum2(float a, float b) {
    __shared__ float sa[32], sb[32];
    int lane = threadIdx.x & 31, wid = threadIdx.x >> 5;
    #pragma unroll
    for (int o = 16; o; o >>= 1) {
        a += __shfl_xor_sync(0xFFFFFFFFu, a, o);
        b += __shfl_xor_sync(0xFFFFFFFFu, b, o);
    }
    if (lane == 0) { sa[wid] = a; sb[wid] = b; }
    __syncthreads();
    int nw = blockDim.x >> 5;
    a = (threadIdx.x < (unsigned)nw) ? sa[threadIdx.x] : 0.f;
    b = (threadIdx.x < (unsigned)nw) ? sb[threadIdx.x] : 0.f;
    if (wid == 0) {
        #pragma unroll
        for (int o = 16; o; o >>= 1) {
            a += __shfl_xor_sync(0xFFFFFFFFu, a, o);
            b += __shfl_xor_sync(0xFFFFFFFFu, b, o);
        }
    }
    return make_float2(a, b);
}

__device__ __forceinline__ uint32_t smem_u32(const void* p) {
    return (uint32_t)__cvta_generic_to_shared(p);
}

#define CP16(dst, src) asm volatile("cp.async.cg.shared.global [%0], [%1], 16;\n" :: "r"(dst), "l"(src) : "memory")
#define LDSM4(r, addr) asm volatile("ldmatrix.sync.aligned.m8n8.x4.shared.b16 {%0,%1,%2,%3}, [%4];\n" \
    : "=r"((r)[0]), "=r"((r)[1]), "=r"((r)[2]), "=r"((r)[3]) : "r"(addr))
#define MMA16816(d, a, b0, b1) asm volatile( \
    "mma.sync.aligned.m16n8k16.row.col.f32.bf16.bf16.f32 " \
    "{%0,%1,%2,%3},{%4,%5,%6,%7},{%8,%9},{%0,%1,%2,%3};\n" \
    : "+f"((d)[0]), "+f"((d)[1]), "+f"((d)[2]), "+f"((d)[3]) \
    : "r"((a)[0]), "r"((a)[1]), "r"((a)[2]), "r"((a)[3]), "r"(b0), "r"(b1))

// ---------------- kernel 1: prep pred masks ----------------
__global__ void __launch_bounds__(256) prep_k(const float* __restrict__ pm) {
    const int row = blockIdx.x;
    const float4* src = (const float4*)(pm + (size_t)row * POUT);
    uint2* dx = (uint2*)(g_A + (size_t)row * GK);
    uint2* dp = (uint2*)(g_A + (size_t)(row + NROWS) * GK);
    float ls = 0.f, ps = 0.f;
    for (int i = threadIdx.x; i < POUT / 4; i += blockDim.x) {
        float4 v = src[i];
        float x[4] = {v.x, v.y, v.z, v.w};
        float sg[4];
        #pragma unroll
        for (int j = 0; j < 4; j++) {
            float e = __expf(-fabsf(x[j]));              // e^{-|x|}
            float inv = __fdividef(1.f, 1.f + e);
            sg[j] = (x[j] >= 0.f) ? inv : e * inv;       // sigmoid(x)
            ls -= fmaxf(x[j], 0.f) + __logf(1.f + e);    // log_sigmoid(-x) = -softplus(x)
            ps += sg[j];
        }
        __nv_bfloat162 x01, x23, s01, s23;
        x01.x = __float2bfloat16_rn(x[0]);  x01.y = __float2bfloat16_rn(x[1]);
        x23.x = __float2bfloat16_rn(x[2]);  x23.y = __float2bfloat16_rn(x[3]);
        s01.x = __float2bfloat16_rn(sg[0]); s01.y = __float2bfloat16_rn(sg[1]);
        s23.x = __float2bfloat16_rn(sg[2]); s23.y = __float2bfloat16_rn(sg[3]);
        uint2 wx, ws;
        wx.x = *reinterpret_cast<unsigned*>(&x01); wx.y = *reinterpret_cast<unsigned*>(&x23);
        ws.x = *reinterpret_cast<unsigned*>(&s01); ws.y = *reinterpret_cast<unsigned*>(&s23);
        dx[i] = wx;
        dp[i] = ws;
    }
    float2 r = blockReduceSum2(ls, ps);
    if (threadIdx.x == 0) { g_L[row] = r.x; g_P[row] = r.y; }
}

// ---------------- kernel 2: antialiased separable resize 256->160 ----------------
__global__ void __launch_bounds__(256) resize2_k(const float* __restrict__ tm) {
    extern __shared__ float tmp[];   // [160][257] vertical-resized intermediate
    const int t = blockIdx.x;
    const int tid = threadIdx.x;
    const float* src = tm + (size_t)t * (HIN * HIN);
    const float kinv = 1.0f / 1.6f;

    {
        const int x = tid;   // 0..255
        for (int oy = 0; oy < HOUT; oy++) {
            float sy = (oy + 0.5f) * 1.6f - 0.5f;
            int jy0 = (int)ceilf(sy - 1.6f);
            float acc = 0.f, wsum = 0.f;
            #pragma unroll
            for (int r = 0; r < 4; r++) {
                int j = jy0 + r;
                float w = fmaxf(1.f - fabsf(sy - (float)j) * kinv, 0.f);
                if (j < 0 || j > HIN - 1) w = 0.f;
                int jj = min(max(j, 0), HIN - 1);
                acc += w * src[jj * HIN + x];
                wsum += w;
            }
            tmp[oy * RESIZE_LD + x] = acc * __fdividef(1.f, wsum);
        }
    }
    __syncthreads();

    for (int i = tid; i < POUT; i += 256) {
        int oy = i / HOUT, ox = i - oy * HOUT;
        float sx = (ox + 0.5f) * 1.6f - 0.5f;
        int jx0 = (int)ceilf(sx - 1.6f);
        float acc = 0.f, wsum = 0.f;
        #pragma unroll
        for (int c = 0; c < 4; c++) {
            int j = jx0 + c;
            float w = fmaxf(1.f - fabsf(sx - (float)j) * kinv, 0.f);
            if (j < 0 || j > HIN - 1) w = 0.f;
            int jj = min(max(j, 0), HIN - 1);
            acc += w * tmp[oy * RESIZE_LD + jj];
            wsum += w;
        }
        g_T[(size_t)t * GK + i] = __float2bfloat16_rn(acc * __fdividef(1.f, wsum));
    }
}

// ---------------- kernel 3: target mask sums ----------------
__global__ void __launch_bounds__(256) tsum_k() {
    const int t = blockIdx.x;
    const __nv_bfloat16* p = g_T + (size_t)t * GK;
    float s = 0.f;
    for (int i = threadIdx.x; i < POUT; i += 256) s += __bfloat162float(p[i]);
    float2 r = blockReduceSum2(s, 0.f);
    if (threadIdx.x == 0) g_TS[t] = r.x;
}

// ---------------- kernel 4: class softmax ----------------
__global__ void __launch_bounds__(128) softmax_k(const float* __restrict__ logits) {
    const int n = blockIdx.x;
    const int t = threadIdx.x;
    __shared__ float sh[128];
    float v = (t < NC) ? logits[(size_t)n * NC + t] : -1e30f;
    sh[t] = v; __syncthreads();
    #pragma unroll
    for (int s = 64; s; s >>= 1) { if (t < s) sh[t] = fmaxf(sh[t], sh[t + s]); __syncthreads(); }
    float mx = sh[0]; __syncthreads();
    float e = (t < NC) ? expf(v - mx) : 0.f;
    sh[t] = e; __syncthreads();
    #pragma unroll
    for (int s = 64; s; s >>= 1) { if (t < s) sh[t] += sh[t + s]; __syncthreads(); }
    float inv = 1.f / sh[0];
    if (t < NC) g_prob[(size_t)n * NC + t] = e * inv;
}

// ---------------- kernel 5: HMMA GEMM, 148-CTA balanced K-split ----------------
// 148 CTAs: 38 (m,n) tiles; tiles 0..33 -> 4 K-splits, tiles 34..37 -> 3 K-splits.
__global__ void __launch_bounds__(256, 1) gemm_k() {
    extern __shared__ __align__(16) char smem[];
    const uint32_t sb = smem_u32(smem);
    const int tid = threadIdx.x;
    const int bid = blockIdx.x;

    int tile, split, nsplits;
    if (bid < 136) { tile = bid >> 2;            split = bid & 3;       nsplits = 4; }
    else           { int r = bid - 136; tile = 34 + r / 3; split = r % 3; nsplits = 3; }
    const int bm = (tile >> 1) * BM;
    const int bn = (tile & 1) * BN;

    int ch0, nkt;
    if (nsplits == 4) { ch0 = split * 200; nkt = 200; }
    else              { ch0 = split * 267; nkt = (split == 2) ? 266 : 267; }

    const __nv_bfloat16* Ag = g_A + (size_t)bm * GK;

    const int lane = tid & 31, warp = tid >> 5;
    const int wm = (warp >> 2) * 64;        // 0 or 64
    const int wn = (warp & 3) * 64;         // 0,64,128,192
    const int grp = lane >> 3, rr = lane & 7;
    const int aRow = (grp & 1) * 8 + rr, aK = (grp >> 1) * 8;
    const int bRow = (grp >> 1) * 8 + rr, bK = (grp & 1) * 8;

    float acc[4][8][4];
    #pragma unroll
    for (int i = 0; i < 4; i++)
        #pragma unroll
        for (int j = 0; j < 8; j++)
            #pragma unroll
            for (int k = 0; k < 4; k++) acc[i][j][k] = 0.f;

    auto load_stage = [&](int s, int kt) {
        const size_t kbase = (size_t)kt * BK;
        const uint32_t abase = sb + s * SM_STAGE;
        #pragma unroll
        for (int i = 0; i < 2; i++) {                       // A: 512 x 16B chunks
            int c = tid + i * 256;
            int r = c >> 2, seg = c & 3;
            CP16(abase + (uint32_t)(r * LDKROW + seg * 8) * 2, Ag + (size_t)r * GK + kbase + seg * 8);
        }
        const uint32_t bbase = abase + SM_A_BYTES;
        #pragma unroll
        for (int i = 0; i < 4; i++) {                       // B: 1024 x 16B chunks
            int c = tid + i * 256;
            int r = c >> 2, seg = c & 3;
            CP16(bbase + (uint32_t)(r * LDKROW + seg * 8) * 2,
                 g_T + (size_t)(bn + r) * GK + kbase + seg * 8);
        }
        asm volatile("cp.async.commit_group;\n" ::: "memory");
    };

    load_stage(0, ch0 + 0);
    load_stage(1, ch0 + 1);
    load_stage(2, ch0 + 2);

    for (int kt = 0; kt < nkt; kt++) {
        const int s = kt & 3;
        const int rem = nkt - kt;
        if (rem >= 3)      { asm volatile("cp.async.wait_group 2;\n" ::: "memory"); }
        else if (rem == 2) { asm volatile("cp.async.wait_group 1;\n" ::: "memory"); }
        else               { asm volatile("cp.async.wait_group 0;\n" ::: "memory"); }
        __syncthreads();   // data visible + all warps done reading stage (kt+3)&3
        if (kt + 3 < nkt) load_stage((kt + 3) & 3, ch0 + kt + 3);

        const uint32_t abase = sb + s * SM_STAGE;
        const uint32_t bbase = abase + SM_A_BYTES;
        #pragma unroll
        for (int kk = 0; kk < BK; kk += 16) {
            uint32_t a[4][4], b[4][4];
            #pragma unroll
            for (int mi = 0; mi < 4; mi++) {
                uint32_t ad = abase + (uint32_t)((wm + mi * 16 + aRow) * LDKROW + kk + aK) * 2;
                LDSM4(a[mi], ad);
            }
            #pragma unroll
            for (int bi = 0; bi < 4; bi++) {
                uint32_t bd = bbase + (uint32_t)((wn + bi * 16 + bRow) * LDKROW + kk + bK) * 2;
                LDSM4(b[bi], bd);
            }
            #pragma unroll
            for (int mi = 0; mi < 4; mi++)
                #pragma unroll
                for (int ni = 0; ni < 8; ni++) {
                    const uint32_t* bb = &b[ni >> 1][(ni & 1) * 2];
                    MMA16816(acc[mi][ni], a[mi], bb[0], bb[1]);
                }
        }
        // no trailing sync: next iteration's top barrier orders stage reuse
    }

    // epilogue: write K-split partial tile
    const int g = lane >> 2, tg = lane & 3;
    float* Sp = g_Sp + (size_t)split * GM * GN;
    #pragma unroll
    for (int mi = 0; mi < 4; mi++)
        #pragma unroll
        for (int ni = 0; ni < 8; ni++) {
            size_t row = (size_t)(bm + wm + mi * 16 + g);
            int col = bn + wn + ni * 8 + tg * 2;
            *(float2*)&Sp[row * GN + col] = make_float2(acc[mi][ni][0], acc[mi][ni][1]);
            *(float2*)&Sp[(row + 8) * GN + col] = make_float2(acc[mi][ni][2], acc[mi][ni][3]);
        }
}

// ---------------- kernel 6: combine (incl. K-split reduction) ----------------
__global__ void __launch_bounds__(128) combine_k(const float* __restrict__ pboxes,
                                                 const float* __restrict__ tboxes,
                                                 const int* __restrict__ tids,
                                                 float* __restrict__ out) {
    const int n = blockIdx.y;
    const int m = blockIdx.x * 128 + threadIdx.x;
    if (m >= MT) return;

    const float4 pb = reinterpret_cast<const float4*>(pboxes)[n];
    const float4 tb = reinterpret_cast<const float4*>(tboxes)[m];

    float cost_bbox = fabsf(pb.x - tb.x) + fabsf(pb.y - tb.y) + fabsf(pb.z - tb.z) + fabsf(pb.w - tb.w);

    float px0 = pb.x - 0.5f * pb.z, py0 = pb.y - 0.5f * pb.w;
    float px1 = pb.x + 0.5f * pb.z, py1 = pb.y + 0.5f * pb.w;
    float tx0 = tb.x - 0.5f * tb.z, ty0 = tb.y - 0.5f * tb.w;
    float tx1 = tb.x + 0.5f * tb.z, ty1 = tb.y + 0.5f * tb.w;
    float area1 = (px1 - px0) * (py1 - py0);
    float area2 = (tx1 - tx0) * (ty1 - ty0);
    float lx = fmaxf(px0, tx0), ly = fmaxf(py0, ty0);
    float rx = fminf(px1, tx1), ry = fminf(py1, ty1);
    float iw = fmaxf(rx - lx, 0.f), ih = fmaxf(ry - ly, 0.f);
    float inter = iw * ih;
    float uni = area1 + area2 - inter;
    float iou = inter / uni;
    float ex = fminf(px0, tx0), ey = fminf(py0, ty0);
    float fx2 = fmaxf(px1, tx1), fy2 = fmaxf(py1, ty1);
    float ew = fmaxf(fx2 - ex, 0.f), eh = fmaxf(fy2 - ey, 0.f);
    float areae = ew * eh;
    float giou = iou - (areae - uni) / areae;

    int id = tids[m];
    float cclass = -g_prob[(size_t)n * NC + id];

    float s1 = 0.f, s2 = 0.f;
    #pragma unroll
    for (int s = 0; s < MAXSPLIT; s++) {
        s1 += g_Sp[((size_t)s * GM + n) * GN + m];
        s2 += g_Sp[((size_t)s * GM + n + NROWS) * GN + m];
    }

    float cmask = -(s1 + g_L[n]) / (float)POUT;
    float cdice = 1.f - (2.f * s2 + 1e-5f) / (g_P[n] + g_TS[m] + 1e-5f);

    out[(size_t)n * MT + m] = 5.f * cost_bbox + 2.f * (-giou) + 2.f * cclass
                            + 5.f * cmask + 5.f * cdice;
}

// ---------------- launch ----------------
extern "C" void kernel_launch(void* const* d_in, const int* in_sizes, int n_in,
                              void* d_out, int out_size) {
    (void)in_sizes; (void)n_in; (void)out_size;
    const float* logits = (const float*)d_in[0];
    const float* pboxes = (const float*)d_in[1];
    const float* pmasks = (const float*)d_in[2];
    const float* tboxes = (const float*)d_in[3];
    const float* tmasks = (const float*)d_in[4];
    const int*   tids   = (const int*)d_in[5];
    float* out = (float*)d_out;

    cudaFuncSetAttribute(gemm_k, cudaFuncAttributeMaxDynamicSharedMemorySize, GEMM_SMEM);
    cudaFuncSetAttribute(resize2_k, cudaFuncAttributeMaxDynamicSharedMemorySize, RESIZE_SMEM);

    // NOTE: gemm is launch index 3 so the harness's ncu window (-s/-c) captures it.
    prep_k<<<NROWS, 256>>>(pmasks);
    resize2_k<<<MT, 256, RESIZE_SMEM>>>(tmasks);
    tsum_k<<<MT, 256>>>();
    gemm_k<<<148, 256, GEMM_SMEM>>>();
    softmax_k<<<NROWS, 128>>>(logits);
    combine_k<<<dim3((MT + 127) / 128, NROWS), 128>>>(pboxes, tboxes, tids, out);
}

// round 10
// speedup vs baseline: 1.2516x; 1.2516x over previous
#include <cuda_runtime.h>
#include <cuda_bf16.h>
#include <cstdint>

// ---------------- problem constants ----------------
#define NC     81
#define NROWS  1200          // B*Q
#define HOUT   160
#define POUT   25600         // 160*160
#define MT     400           // num targets
#define HIN    256

// ---------------- GEMM constants -------------------
#define GM 2432              // 2*1200 padded to 19*128
#define GN 512               // 400 padded to 2*256
#define GK 25600
#define BM 128
#define BN 256
#define BK 32
#define MAXSPLIT 4
#define STAGES 4
#define LDKROW 40            // padded smem row: 40 bf16 = 80B
#define GTHREADS 512

#define SM_A_BYTES (BM * LDKROW * 2)              // 10240
#define SM_B_BYTES (BN * LDKROW * 2)              // 20480
#define SM_STAGE   (SM_A_BYTES + SM_B_BYTES)      // 30720
#define GEMM_SMEM  (STAGES * SM_STAGE)            // 122880

// resize chunking: 32 output rows per CTA, 5 chunks per mask
#define RROWS 32
#define RCHUNKS (HOUT / RROWS)                    // 5
#define RESIZE_LD 257
#define RESIZE_SMEM (RROWS * RESIZE_LD * 4)       // 32896

// ---------------- scratch (device globals; zero-initialized) ----------------
__device__ __align__(16) __nv_bfloat16 g_A[(size_t)GM * GK];  // [X; sigmoid(X)], pad rows 0
__device__ __align__(16) __nv_bfloat16 g_T[(size_t)GN * GK];  // resized targets, pad rows 0
__device__ float g_Sp[(size_t)MAXSPLIT * GM * GN];            // K-split partials (unwritten stay 0)
__device__ float g_L[NROWS];                                  // rowsum log_sigmoid(-x)
__device__ float g_P[NROWS];                                  // rowsum sigmoid(x)
__device__ float g_TS[MT];                                    // target mask sums
__device__ float g_prob[NROWS * NC];                          // softmax probs

// ---------------- helpers ----------------
__device__ __forceinline__ float2 blockReduceSum2(float a, float b) {
    __shared__ float sa[32], sb[32];
    int lane = threadIdx.x & 31, wid = threadIdx.x >> 5;
    #pragma unroll
    for (int o = 16; o; o >>= 1) {
        a += __shfl_xor_sync(0xFFFFFFFFu, a, o);
        b += __shfl_xor_sync(0xFFFFFFFFu, b, o);
    }
    if (lane == 0) { sa[wid] = a; sb[wid] = b; }
    __syncthreads();
    int nw = blockDim.x >> 5;
    a = (threadIdx.x < (unsigned)nw) ? sa[threadIdx.x] : 0.f;
    b = (threadIdx.x < (unsigned)nw) ? sb[threadIdx.x] : 0.f;
    if (wid == 0) {
        #pragma unroll
        for (int o = 16; o; o >>= 1) {
            a += __shfl_xor_sync(0xFFFFFFFFu, a, o);
            b += __shfl_xor_sync(0xFFFFFFFFu, b, o);
        }
    }
    return make_float2(a, b);
}

__device__ __forceinline__ uint32_t smem_u32(const void* p) {
    return (uint32_t)__cvta_generic_to_shared(p);
}

#define CP16(dst, src) asm volatile("cp.async.cg.shared.global [%0], [%1], 16;\n" :: "r"(dst), "l"(src) : "memory")
#define LDSM4(r, addr) asm volatile("ldmatrix.sync.aligned.m8n8.x4.shared.b16 {%0,%1,%2,%3}, [%4];\n" \
    : "=r"((r)[0]), "=r"((r)[1]), "=r"((r)[2]), "=r"((r)[3]) : "r"(addr))
#define MMA16816(d, a, b0, b1) asm volatile( \
    "mma.sync.aligned.m16n8k16.row.col.f32.bf16.bf16.f32 " \
    "{%0,%1,%2,%3},{%4,%5,%6,%7},{%8,%9},{%0,%1,%2,%3};\n" \
    : "+f"((d)[0]), "+f"((d)[1]), "+f"((d)[2]), "+f"((d)[3]) \
    : "r"((a)[0]), "r"((a)[1]), "r"((a)[2]), "r"((a)[3]), "r"(b0), "r"(b1))

// ---------------- kernel 1: prep pred masks ----------------
__global__ void __launch_bounds__(256) prep_k(const float* __restrict__ pm) {
    const int row = blockIdx.x;
    const float4* src = (const float4*)(pm + (size_t)row * POUT);
    uint2* dx = (uint2*)(g_A + (size_t)row * GK);
    uint2* dp = (uint2*)(g_A + (size_t)(row + NROWS) * GK);
    float ls = 0.f, ps = 0.f;
    for (int i = threadIdx.x; i < POUT / 4; i += blockDim.x) {
        float4 v = src[i];
        float x[4] = {v.x, v.y, v.z, v.w};
        float sg[4];
        #pragma unroll
        for (int j = 0; j < 4; j++) {
            float e = __expf(-fabsf(x[j]));              // e^{-|x|}
            float inv = __fdividef(1.f, 1.f + e);
            sg[j] = (x[j] >= 0.f) ? inv : e * inv;       // sigmoid(x)
            ls -= fmaxf(x[j], 0.f) + __logf(1.f + e);    // log_sigmoid(-x) = -softplus(x)
            ps += sg[j];
        }
        __nv_bfloat162 x01, x23, s01, s23;
        x01.x = __float2bfloat16_rn(x[0]);  x01.y = __float2bfloat16_rn(x[1]);
        x23.x = __float2bfloat16_rn(x[2]);  x23.y = __float2bfloat16_rn(x[3]);
        s01.x = __float2bfloat16_rn(sg[0]); s01.y = __float2bfloat16_rn(sg[1]);
        s23.x = __float2bfloat16_rn(sg[2]); s23.y = __float2bfloat16_rn(sg[3]);
        uint2 wx, ws;
        wx.x = *reinterpret_cast<unsigned*>(&x01); wx.y = *reinterpret_cast<unsigned*>(&x23);
        ws.x = *reinterpret_cast<unsigned*>(&s01); ws.y = *reinterpret_cast<unsigned*>(&s23);
        dx[i] = wx;
        dp[i] = ws;
    }
    float2 r = blockReduceSum2(ls, ps);
    if (threadIdx.x == 0) { g_L[row] = r.x; g_P[row] = r.y; }
}

// ---------------- kernel 2: antialiased separable resize 256->160, chunked ---------
// grid (RCHUNKS, MT): each CTA does 32 output rows of one mask. 33KB smem -> ~6 CTAs/SM.
__global__ void __launch_bounds__(256) resize2_k(const float* __restrict__ tm) {
    __shared__ float tmp[RROWS * RESIZE_LD];
    const int chunk = blockIdx.x;
    const int t = blockIdx.y;
    const int oy0 = chunk * RROWS;
    const int tid = threadIdx.x;
    const float* src = tm + (size_t)t * (HIN * HIN);
    const float kinv = 1.0f / 1.6f;

    // pass 1: vertical resize for rows oy0..oy0+31, all 256 columns (x = tid)
    {
        const int x = tid;
        #pragma unroll 4
        for (int r = 0; r < RROWS; r++) {
            int oy = oy0 + r;
            float sy = (oy + 0.5f) * 1.6f - 0.5f;
            int jy0 = (int)ceilf(sy - 1.6f);
            float acc = 0.f, wsum = 0.f;
            #pragma unroll
            for (int k = 0; k < 4; k++) {
                int j = jy0 + k;
                float w = fmaxf(1.f - fabsf(sy - (float)j) * kinv, 0.f);
                if (j < 0 || j > HIN - 1) w = 0.f;
                int jj = min(max(j, 0), HIN - 1);
                acc += w * src[jj * HIN + x];
                wsum += w;
            }
            tmp[r * RESIZE_LD + x] = acc * __fdividef(1.f, wsum);
        }
    }
    __syncthreads();

    // pass 2: horizontal resize for the 32x160 output block
    for (int i = tid; i < RROWS * HOUT; i += 256) {
        int r = i / HOUT, ox = i - r * HOUT;
        float sx = (ox + 0.5f) * 1.6f - 0.5f;
        int jx0 = (int)ceilf(sx - 1.6f);
        float acc = 0.f, wsum = 0.f;
        #pragma unroll
        for (int c = 0; c < 4; c++) {
            int j = jx0 + c;
            float w = fmaxf(1.f - fabsf(sx - (float)j) * kinv, 0.f);
            if (j < 0 || j > HIN - 1) w = 0.f;
            int jj = min(max(j, 0), HIN - 1);
            acc += w * tmp[r * RESIZE_LD + jj];
            wsum += w;
        }
        g_T[(size_t)t * GK + (oy0 + r) * HOUT + ox] = __float2bfloat16_rn(acc * __fdividef(1.f, wsum));
    }
}

// ---------------- kernel 3: target mask sums ----------------
__global__ void __launch_bounds__(256) tsum_k() {
    const int t = blockIdx.x;
    const __nv_bfloat16* p = g_T + (size_t)t * GK;
    float s = 0.f;
    for (int i = threadIdx.x; i < POUT; i += 256) s += __bfloat162float(p[i]);
    float2 r = blockReduceSum2(s, 0.f);
    if (threadIdx.x == 0) g_TS[t] = r.x;
}

// ---------------- kernel 4: class softmax ----------------
__global__ void __launch_bounds__(128) softmax_k(const float* __restrict__ logits) {
    const int n = blockIdx.x;
    const int t = threadIdx.x;
    __shared__ float sh[128];
    float v = (t < NC) ? logits[(size_t)n * NC + t] : -1e30f;
    sh[t] = v; __syncthreads();
    #pragma unroll
    for (int s = 64; s; s >>= 1) { if (t < s) sh[t] = fmaxf(sh[t], sh[t + s]); __syncthreads(); }
    float mx = sh[0]; __syncthreads();
    float e = (t < NC) ? expf(v - mx) : 0.f;
    sh[t] = e; __syncthreads();
    #pragma unroll
    for (int s = 64; s; s >>= 1) { if (t < s) sh[t] += sh[t + s]; __syncthreads(); }
    float inv = 1.f / sh[0];
    if (t < NC) g_prob[(size_t)n * NC + t] = e * inv;
}

// ---------------- kernel 5: HMMA GEMM, 16 warps/CTA, 148-CTA K-split ----------------
// 148 CTAs: 38 (m,n) tiles; tiles 0..33 -> 4 K-splits, tiles 34..37 -> 3 K-splits.
// 512 threads = 16 warps as 4m x 4n of 32x64 warp tiles over the 128x256 CTA tile.
__global__ void __launch_bounds__(GTHREADS, 1) gemm_k() {
    extern __shared__ __align__(16) char smem[];
    const uint32_t sb = smem_u32(smem);
    const int tid = threadIdx.x;
    const int bid = blockIdx.x;

    int tile, split, nsplits;
    if (bid < 136) { tile = bid >> 2;            split = bid & 3;       nsplits = 4; }
    else           { int r = bid - 136; tile = 34 + r / 3; split = r % 3; nsplits = 3; }
    const int bm = (tile >> 1) * BM;
    const int bn = (tile & 1) * BN;

    int ch0, nkt;
    if (nsplits == 4) { ch0 = split * 200; nkt = 200; }
    else              { ch0 = split * 267; nkt = (split == 2) ? 266 : 267; }

    const __nv_bfloat16* Ag = g_A + (size_t)bm * GK;

    const int lane = tid & 31, warp = tid >> 5;
    const int wm = (warp >> 2) * 32;        // 0,32,64,96
    const int wn = (warp & 3) * 64;         // 0,64,128,192
    const int grp = lane >> 3, rr = lane & 7;
    const int aRow = (grp & 1) * 8 + rr, aK = (grp >> 1) * 8;
    const int bRow = (grp >> 1) * 8 + rr, bK = (grp & 1) * 8;

    float acc[2][8][4];
    #pragma unroll
    for (int i = 0; i < 2; i++)
        #pragma unroll
        for (int j = 0; j < 8; j++)
            #pragma unroll
            for (int k = 0; k < 4; k++) acc[i][j][k] = 0.f;

    auto load_stage = [&](int s, int kt) {
        const size_t kbase = (size_t)kt * BK;
        const uint32_t abase = sb + s * SM_STAGE;
        {                                                   // A: 512 x 16B chunks, 1/thread
            int r = tid >> 2, seg = tid & 3;
            CP16(abase + (uint32_t)(r * LDKROW + seg * 8) * 2, Ag + (size_t)r * GK + kbase + seg * 8);
        }
        const uint32_t bbase = abase + SM_A_BYTES;
        #pragma unroll
        for (int i = 0; i < 2; i++) {                       // B: 1024 x 16B chunks, 2/thread
            int c = tid + i * GTHREADS;
            int r = c >> 2, seg = c & 3;
            CP16(bbase + (uint32_t)(r * LDKROW + seg * 8) * 2,
                 g_T + (size_t)(bn + r) * GK + kbase + seg * 8);
        }
        asm volatile("cp.async.commit_group;\n" ::: "memory");
    };

    load_stage(0, ch0 + 0);
    load_stage(1, ch0 + 1);
    load_stage(2, ch0 + 2);

    for (int kt = 0; kt < nkt; kt++) {
        const int s = kt & 3;
        const int rem = nkt - kt;
        if (rem >= 3)      { asm volatile("cp.async.wait_group 2;\n" ::: "memory"); }
        else if (rem == 2) { asm volatile("cp.async.wait_group 1;\n" ::: "memory"); }
        else               { asm volatile("cp.async.wait_group 0;\n" ::: "memory"); }
        __syncthreads();   // data visible + all warps done reading stage (kt+3)&3
        if (kt + 3 < nkt) load_stage((kt + 3) & 3, ch0 + kt + 3);

        const uint32_t abase = sb + s * SM_STAGE;
        const uint32_t bbase = abase + SM_A_BYTES;
        #pragma unroll
        for (int kk = 0; kk < BK; kk += 16) {
            uint32_t a[2][4], b[4][4];
            #pragma unroll
            for (int mi = 0; mi < 2; mi++) {
                uint32_t ad = abase + (uint32_t)((wm + mi * 16 + aRow) * LDKROW + kk + aK) * 2;
                LDSM4(a[mi], ad);
            }
            #pragma unroll
            for (int bi = 0; bi < 4; bi++) {
                uint32_t bd = bbase + (uint32_t)((wn + bi * 16 + bRow) * LDKROW + kk + bK) * 2;
                LDSM4(b[bi], bd);
            }
            #pragma unroll
            for (int mi = 0; mi < 2; mi++)
                #pragma unroll
                for (int ni = 0; ni < 8; ni++) {
                    const uint32_t* bb = &b[ni >> 1][(ni & 1) * 2];
                    MMA16816(acc[mi][ni], a[mi], bb[0], bb[1]);
                }
        }
        // no trailing sync: next iteration's top barrier orders stage reuse
    }

    // epilogue: write K-split partial tile
    const int g = lane >> 2, tg = lane & 3;
    float* Sp = g_Sp + (size_t)split * GM * GN;
    #pragma unroll
    for (int mi = 0; mi < 2; mi++)
        #pragma unroll
        for (int ni = 0; ni < 8; ni++) {
            size_t row = (size_t)(bm + wm + mi * 16 + g);
            int col = bn + wn + ni * 8 + tg * 2;
            *(float2*)&Sp[row * GN + col] = make_float2(acc[mi][ni][0], acc[mi][ni][1]);
            *(float2*)&Sp[(row + 8) * GN + col] = make_float2(acc[mi][ni][2], acc[mi][ni][3]);
        }
}

// ---------------- kernel 6: combine (incl. K-split reduction) ----------------
__global__ void __launch_bounds__(128) combine_k(const float* __restrict__ pboxes,
                                                 const float* __restrict__ tboxes,
                                                 const int* __restrict__ tids,
                                                 float* __restrict__ out) {
    const int n = blockIdx.y;
    const int m = blockIdx.x * 128 + threadIdx.x;
    if (m >= MT) return;

    const float4 pb = reinterpret_cast<const float4*>(pboxes)[n];
    const float4 tb = reinterpret_cast<const float4*>(tboxes)[m];

    float cost_bbox = fabsf(pb.x - tb.x) + fabsf(pb.y - tb.y) + fabsf(pb.z - tb.z) + fabsf(pb.w - tb.w);

    float px0 = pb.x - 0.5f * pb.z, py0 = pb.y - 0.5f * pb.w;
    float px1 = pb.x + 0.5f * pb.z, py1 = pb.y + 0.5f * pb.w;
    float tx0 = tb.x - 0.5f * tb.z, ty0 = tb.y - 0.5f * tb.w;
    float tx1 = tb.x + 0.5f * tb.z, ty1 = tb.y + 0.5f * tb.w;
    float area1 = (px1 - px0) * (py1 - py0);
    float area2 = (tx1 - tx0) * (ty1 - ty0);
    float lx = fmaxf(px0, tx0), ly = fmaxf(py0, ty0);
    float rx = fminf(px1, tx1), ry = fminf(py1, ty1);
    float iw = fmaxf(rx - lx, 0.f), ih = fmaxf(ry - ly, 0.f);
    float inter = iw * ih;
    float uni = area1 + area2 - inter;
    float iou = inter / uni;
    float ex = fminf(px0, tx0), ey = fminf(py0, ty0);
    float fx2 = fmaxf(px1, tx1), fy2 = fmaxf(py1, ty1);
    float ew = fmaxf(fx2 - ex, 0.f), eh = fmaxf(fy2 - ey, 0.f);
    float areae = ew * eh;
    float giou = iou - (areae - uni) / areae;

    int id = tids[m];
    float cclass = -g_prob[(size_t)n * NC + id];

    float s1 = 0.f, s2 = 0.f;
    #pragma unroll
    for (int s = 0; s < MAXSPLIT; s++) {
        s1 += g_Sp[((size_t)s * GM + n) * GN + m];
        s2 += g_Sp[((size_t)s * GM + n + NROWS) * GN + m];
    }

    float cmask = -(s1 + g_L[n]) / (float)POUT;
    float cdice = 1.f - (2.f * s2 + 1e-5f) / (g_P[n] + g_TS[m] + 1e-5f);

    out[(size_t)n * MT + m] = 5.f * cost_bbox + 2.f * (-giou) + 2.f * cclass
                            + 5.f * cmask + 5.f * cdice;
}

// ---------------- launch ----------------
extern "C" void kernel_launch(void* const* d_in, const int* in_sizes, int n_in,
                              void* d_out, int out_size) {
    (void)in_sizes; (void)n_in; (void)out_size;
    const float* logits = (const float*)d_in[0];
    const float* pboxes = (const float*)d_in[1];
    const float* pmasks = (const float*)d_in[2];
    const float* tboxes = (const float*)d_in[3];
    const float* tmasks = (const float*)d_in[4];
    const int*   tids   = (const int*)d_in[5];
    float* out = (float*)d_out;

    cudaFuncSetAttribute(gemm_k, cudaFuncAttributeMaxDynamicSharedMemorySize, GEMM_SMEM);

    // NOTE: gemm is launch index 3 so the harness's ncu window (-s/-c) captures it.
    prep_k<<<NROWS, 256>>>(pmasks);
    resize2_k<<<dim3(RCHUNKS, MT), 256>>>(tmasks);
    tsum_k<<<MT, 256>>>();
    gemm_k<<<148, GTHREADS, GEMM_SMEM>>>();
    softmax_k<<<NROWS, 128>>>(logits);
    combine_k<<<dim3((MT + 127) / 128, NROWS), 128>>>(pboxes, tboxes, tids, out);
}